// round 2
// baseline (speedup 1.0000x reference)
#include <cuda_runtime.h>
#include <math.h>

#define BB 4
#define TT 2048
#define HH 12
#define DK 64
#define DM 768
#define BT (BB*TT)

// Scratch (device globals — no allocations allowed)
__device__ float g_qh[(size_t)BB*HH*TT*DK];   // [B,H,T,64]
__device__ float g_kh[(size_t)BB*HH*TT*DK];
__device__ float g_vh[(size_t)BB*HH*TT*DK];
__device__ float g_cat[(size_t)BT*DM];        // [B,T,768]

// ---------------------------------------------------------------------------
// Kernel 1: per-head QKV projection.
// grid (BT/64, H, 3), block 256. Computes out[b,h,t,e] = x[b,t,h,:]·W[e,:] + b[e]
// 64x64 output tile per block, k=64 single step, 4x4 register tile per thread.
// ---------------------------------------------------------------------------
__global__ __launch_bounds__(256) void proj_kernel(
    const float* __restrict__ q, const float* __restrict__ k, const float* __restrict__ v,
    const float* __restrict__ Wq, const float* __restrict__ bq,
    const float* __restrict__ Wk, const float* __restrict__ bk,
    const float* __restrict__ Wv, const float* __restrict__ bv)
{
    __shared__ float At[64*64];   // At[d][r] = x row r, dim d (transposed)
    __shared__ float Wt[64*64];   // Wt[d][e] = W[e][d]   (transposed)
    __shared__ float bs[64];

    int which = blockIdx.z;
    const float* x    = (which==0) ? q  : (which==1) ? k  : v;
    const float* W    = (which==0) ? Wq : (which==1) ? Wk : Wv;
    const float* bias = (which==0) ? bq : (which==1) ? bk : bv;
    float* outp       = (which==0) ? g_qh : (which==1) ? g_kh : g_vh;

    int h    = blockIdx.y;
    int row0 = blockIdx.x * 64;
    int t    = threadIdx.x;
    int r    = t & 63, dq = t >> 6;

    {
        const float* xr = x + (size_t)(row0 + r)*DM + h*64 + dq*16;
        #pragma unroll
        for (int u = 0; u < 4; u++) {
            float4 g = *(const float4*)(xr + u*4);
            int d = dq*16 + u*4;
            At[(d+0)*64 + r] = g.x; At[(d+1)*64 + r] = g.y;
            At[(d+2)*64 + r] = g.z; At[(d+3)*64 + r] = g.w;
        }
        const float* wr = W + r*64 + dq*16;
        #pragma unroll
        for (int u = 0; u < 4; u++) {
            float4 g = *(const float4*)(wr + u*4);
            int d = dq*16 + u*4;
            Wt[(d+0)*64 + r] = g.x; Wt[(d+1)*64 + r] = g.y;
            Wt[(d+2)*64 + r] = g.z; Wt[(d+3)*64 + r] = g.w;
        }
        if (t < 64) bs[t] = bias[t];
    }
    __syncthreads();

    int ty = t >> 4, tx = t & 15;
    float acc[4][4] = {};
    #pragma unroll 16
    for (int kk = 0; kk < 64; kk++) {
        float4 a4 = *(const float4*)&At[kk*64 + ty*4];
        float4 b4 = *(const float4*)&Wt[kk*64 + tx*4];
        float av[4] = {a4.x, a4.y, a4.z, a4.w};
        float bv4[4] = {b4.x, b4.y, b4.z, b4.w};
        #pragma unroll
        for (int i = 0; i < 4; i++)
            #pragma unroll
            for (int j = 0; j < 4; j++)
                acc[i][j] += av[i] * bv4[j];
    }

    int b_ = row0 / TT;
    #pragma unroll
    for (int i = 0; i < 4; i++) {
        int row = row0 + ty*4 + i;
        int tok = row - b_*TT;
        float4 o4;
        o4.x = acc[i][0] + bs[tx*4+0];
        o4.y = acc[i][1] + bs[tx*4+1];
        o4.z = acc[i][2] + bs[tx*4+2];
        o4.w = acc[i][3] + bs[tx*4+3];
        *(float4*)(outp + ((size_t)(b_*HH + h)*TT + tok)*DK + tx*4) = o4;
    }
}

// ---------------------------------------------------------------------------
// Kernel 2: flash-style attention.
// grid (T/64, B*H), block 256. Each block: 64 q-rows of one (b,h).
// Online softmax over kv tiles of 64. 4x4 register tile per thread.
// Dynamic smem: Qt/Kt/Vs/Pt, 4 * 64*64 floats = 64KB.
// ---------------------------------------------------------------------------
__global__ __launch_bounds__(256) void attn_kernel()
{
    extern __shared__ float sm[];
    float* Qt = sm;                 // Qt[d][r]
    float* Kt = sm + 4096;          // Kt[d][c]
    float* Vs = sm + 8192;          // Vs[c][d]
    float* Pt = sm + 12288;         // Pt[c][r]

    int bh = blockIdx.y;
    int q0 = blockIdx.x * 64;
    const float* Qb = g_qh + (size_t)bh*TT*DK;
    const float* Kb = g_kh + (size_t)bh*TT*DK;
    const float* Vb = g_vh + (size_t)bh*TT*DK;

    int t  = threadIdx.x;
    int r  = t & 63, dq = t >> 6;
    int ty = t >> 4, tx = t & 15;

    // load Q tile transposed
    {
        const float* qr = Qb + (size_t)(q0 + r)*DK + dq*16;
        #pragma unroll
        for (int u = 0; u < 4; u++) {
            float4 g = *(const float4*)(qr + u*4);
            int d = dq*16 + u*4;
            Qt[(d+0)*64 + r] = g.x; Qt[(d+1)*64 + r] = g.y;
            Qt[(d+2)*64 + r] = g.z; Qt[(d+3)*64 + r] = g.w;
        }
    }

    float o[4][4] = {};
    float m[4], l[4];
    #pragma unroll
    for (int i = 0; i < 4; i++) { m[i] = -INFINITY; l[i] = 0.0f; }
    const float scale = 0.125f;   // 1/sqrt(64)

    for (int kv0 = 0; kv0 < TT; kv0 += 64) {
        __syncthreads();   // previous iteration done reading Kt/Vs/Pt
        {
            const float* kr = Kb + (size_t)(kv0 + r)*DK + dq*16;
            #pragma unroll
            for (int u = 0; u < 4; u++) {
                float4 g = *(const float4*)(kr + u*4);
                int d = dq*16 + u*4;
                Kt[(d+0)*64 + r] = g.x; Kt[(d+1)*64 + r] = g.y;
                Kt[(d+2)*64 + r] = g.z; Kt[(d+3)*64 + r] = g.w;
            }
            const float* vr = Vb + (size_t)(kv0 + r)*DK + dq*16;
            #pragma unroll
            for (int u = 0; u < 4; u++)
                *(float4*)&Vs[r*64 + dq*16 + u*4] = *(const float4*)(vr + u*4);
        }
        __syncthreads();

        // S = Q K^T (64x64 tile), 4x4 per thread
        float s[4][4] = {};
        #pragma unroll 16
        for (int kk = 0; kk < 64; kk++) {
            float4 a4 = *(const float4*)&Qt[kk*64 + ty*4];
            float4 b4 = *(const float4*)&Kt[kk*64 + tx*4];
            float av[4] = {a4.x, a4.y, a4.z, a4.w};
            float bv4[4] = {b4.x, b4.y, b4.z, b4.w};
            #pragma unroll
            for (int i = 0; i < 4; i++)
                #pragma unroll
                for (int j = 0; j < 4; j++)
                    s[i][j] += av[i] * bv4[j];
        }
        #pragma unroll
        for (int i = 0; i < 4; i++)
            #pragma unroll
            for (int j = 0; j < 4; j++)
                s[i][j] *= scale;

        // row max across the 16 lanes sharing each row (tx dimension)
        float rowmax[4];
        #pragma unroll
        for (int i = 0; i < 4; i++) {
            rowmax[i] = fmaxf(fmaxf(s[i][0], s[i][1]), fmaxf(s[i][2], s[i][3]));
        }
        #pragma unroll
        for (int off = 1; off < 16; off <<= 1) {
            #pragma unroll
            for (int i = 0; i < 4; i++)
                rowmax[i] = fmaxf(rowmax[i], __shfl_xor_sync(0xffffffffu, rowmax[i], off));
        }

        float fac[4], psum[4];
        #pragma unroll
        for (int i = 0; i < 4; i++) {
            float mn = fmaxf(m[i], rowmax[i]);
            fac[i] = __expf(m[i] - mn);
            m[i] = mn;
            psum[i] = 0.0f;
        }
        #pragma unroll
        for (int i = 0; i < 4; i++)
            #pragma unroll
            for (int j = 0; j < 4; j++) {
                s[i][j] = __expf(s[i][j] - m[i]);
                psum[i] += s[i][j];
            }
        #pragma unroll
        for (int off = 1; off < 16; off <<= 1) {
            #pragma unroll
            for (int i = 0; i < 4; i++)
                psum[i] += __shfl_xor_sync(0xffffffffu, psum[i], off);
        }
        #pragma unroll
        for (int i = 0; i < 4; i++)
            l[i] = l[i]*fac[i] + psum[i];
        #pragma unroll
        for (int i = 0; i < 4; i++)
            #pragma unroll
            for (int j = 0; j < 4; j++)
                o[i][j] *= fac[i];

        // write P transposed: Pt[c][r]
        #pragma unroll
        for (int j = 0; j < 4; j++) {
            float4 pv = make_float4(s[0][j], s[1][j], s[2][j], s[3][j]);
            *(float4*)&Pt[(tx*4 + j)*64 + ty*4] = pv;
        }
        __syncthreads();

        // O += P @ V
        #pragma unroll 16
        for (int c = 0; c < 64; c++) {
            float4 p4 = *(const float4*)&Pt[c*64 + ty*4];
            float4 v4 = *(const float4*)&Vs[c*64 + tx*4];
            float pv4[4] = {p4.x, p4.y, p4.z, p4.w};
            float vv4[4] = {v4.x, v4.y, v4.z, v4.w};
            #pragma unroll
            for (int i = 0; i < 4; i++)
                #pragma unroll
                for (int j = 0; j < 4; j++)
                    o[i][j] += pv4[i] * vv4[j];
        }
    }

    // normalize and write to concat buffer [B,T,768]
    int b_ = bh / HH, h_ = bh % HH;
    #pragma unroll
    for (int i = 0; i < 4; i++) {
        float inv = 1.0f / l[i];
        int tok = q0 + ty*4 + i;
        float4 o4 = make_float4(o[i][0]*inv, o[i][1]*inv, o[i][2]*inv, o[i][3]*inv);
        *(float4*)(g_cat + ((size_t)(b_*TT + tok))*DM + h_*64 + tx*4) = o4;
    }
}

// ---------------------------------------------------------------------------
// Kernel 3: output projection  out = concat @ Wo^T + bo
// grid (DM/64, BT/64), block 256. 64x64 tile, 12 k-steps of 64.
// ---------------------------------------------------------------------------
__global__ __launch_bounds__(256) void outproj_kernel(
    const float* __restrict__ Wo, const float* __restrict__ bo, float* __restrict__ outp)
{
    __shared__ float At[64*64];   // At[k][n]
    __shared__ float Btile[64*64];// Bt[k][m] = Wo[m][k]
    int m0 = blockIdx.x * 64, n0 = blockIdx.y * 64;
    int t  = threadIdx.x;
    int r  = t & 63, dq = t >> 6;
    int ty = t >> 4, tx = t & 15;

    float acc[4][4] = {};
    for (int k0 = 0; k0 < DM; k0 += 64) {
        __syncthreads();
        {
            const float* ar = g_cat + (size_t)(n0 + r)*DM + k0 + dq*16;
            #pragma unroll
            for (int u = 0; u < 4; u++) {
                float4 g = *(const float4*)(ar + u*4);
                int d = dq*16 + u*4;
                At[(d+0)*64 + r] = g.x; At[(d+1)*64 + r] = g.y;
                At[(d+2)*64 + r] = g.z; At[(d+3)*64 + r] = g.w;
            }
            const float* br = Wo + (size_t)(m0 + r)*DM + k0 + dq*16;
            #pragma unroll
            for (int u = 0; u < 4; u++) {
                float4 g = *(const float4*)(br + u*4);
                int d = dq*16 + u*4;
                Btile[(d+0)*64 + r] = g.x; Btile[(d+1)*64 + r] = g.y;
                Btile[(d+2)*64 + r] = g.z; Btile[(d+3)*64 + r] = g.w;
            }
        }
        __syncthreads();
        #pragma unroll 16
        for (int kk = 0; kk < 64; kk++) {
            float4 a4 = *(const float4*)&At[kk*64 + ty*4];
            float4 b4 = *(const float4*)&Btile[kk*64 + tx*4];
            float av[4] = {a4.x, a4.y, a4.z, a4.w};
            float bv4[4] = {b4.x, b4.y, b4.z, b4.w};
            #pragma unroll
            for (int i = 0; i < 4; i++)
                #pragma unroll
                for (int j = 0; j < 4; j++)
                    acc[i][j] += av[i] * bv4[j];
        }
    }

    #pragma unroll
    for (int i = 0; i < 4; i++) {
        int n = n0 + ty*4 + i;
        float4 o4;
        o4.x = acc[i][0] + bo[m0 + tx*4 + 0];
        o4.y = acc[i][1] + bo[m0 + tx*4 + 1];
        o4.z = acc[i][2] + bo[m0 + tx*4 + 2];
        o4.w = acc[i][3] + bo[m0 + tx*4 + 3];
        *(float4*)(outp + (size_t)n*DM + m0 + tx*4) = o4;
    }
}

// ---------------------------------------------------------------------------
extern "C" void kernel_launch(void* const* d_in, const int* in_sizes, int n_in,
                              void* d_out, int out_size)
{
    const float* q  = (const float*)d_in[0];
    const float* k  = (const float*)d_in[1];
    const float* v  = (const float*)d_in[2];
    const float* Wq = (const float*)d_in[3];
    const float* bq = (const float*)d_in[4];
    const float* Wk = (const float*)d_in[5];
    const float* bk = (const float*)d_in[6];
    const float* Wv = (const float*)d_in[7];
    const float* bv = (const float*)d_in[8];
    const float* Wo = (const float*)d_in[9];
    const float* bo = (const float*)d_in[10];
    float* outp = (float*)d_out;

    cudaFuncSetAttribute(attn_kernel, cudaFuncAttributeMaxDynamicSharedMemorySize, 64*1024);

    proj_kernel<<<dim3(BT/64, HH, 3), 256>>>(q, k, v, Wq, bq, Wk, bk, Wv, bv);
    attn_kernel<<<dim3(TT/64, BB*HH), 256, 64*1024>>>();
    outproj_kernel<<<dim3(DM/64, BT/64), 256>>>(Wo, bo, outp);
}

// round 4
// speedup vs baseline: 5.8637x; 5.8637x over previous
#include <cuda_runtime.h>
#include <cuda_fp16.h>
#include <math.h>
#include <stdint.h>

#define BB 4
#define TT 2048
#define HH 12
#define DK 64
#define DM 768
#define BT (BB*TT)

// Scratch (device globals — no allocations allowed)
__device__ __half g_qh[(size_t)BB*HH*TT*DK];   // [B*H, T, 64] fp16
__device__ __half g_kh[(size_t)BB*HH*TT*DK];
__device__ __half g_vh[(size_t)BB*HH*TT*DK];
__device__ float  g_cat[(size_t)BT*DM];        // [B,T,768] fp32

// ---------------------------------------------------------------------------
// helpers
// ---------------------------------------------------------------------------
__device__ __forceinline__ uint32_t smaddr(const void* p) {
    return (uint32_t)__cvta_generic_to_shared(p);
}
__device__ __forceinline__ void ldsm4(uint32_t* r, uint32_t a) {
    asm volatile("ldmatrix.sync.aligned.m8n8.x4.shared.b16 {%0,%1,%2,%3}, [%4];"
                 : "=r"(r[0]), "=r"(r[1]), "=r"(r[2]), "=r"(r[3]) : "r"(a));
}
__device__ __forceinline__ void ldsm4t(uint32_t* r, uint32_t a) {
    asm volatile("ldmatrix.sync.aligned.m8n8.x4.trans.shared.b16 {%0,%1,%2,%3}, [%4];"
                 : "=r"(r[0]), "=r"(r[1]), "=r"(r[2]), "=r"(r[3]) : "r"(a));
}
__device__ __forceinline__ void mma16816(float* c,
    uint32_t a0, uint32_t a1, uint32_t a2, uint32_t a3, uint32_t b0, uint32_t b1) {
    asm volatile(
        "mma.sync.aligned.m16n8k16.row.col.f32.f16.f16.f32 "
        "{%0,%1,%2,%3}, {%4,%5,%6,%7}, {%8,%9}, {%0,%1,%2,%3};"
        : "+f"(c[0]), "+f"(c[1]), "+f"(c[2]), "+f"(c[3])
        : "r"(a0), "r"(a1), "r"(a2), "r"(a3), "r"(b0), "r"(b1));
}
__device__ __forceinline__ void cp16(void* dst, const void* src) {
    uint32_t d = smaddr(dst);
    asm volatile("cp.async.cg.shared.global [%0], [%1], 16;" :: "r"(d), "l"(src) : "memory");
}
__device__ __forceinline__ void cp_commit() {
    asm volatile("cp.async.commit_group;" ::: "memory");
}
template<int N> __device__ __forceinline__ void cp_wait() {
    asm volatile("cp.async.wait_group %0;" :: "n"(N) : "memory");
}
__device__ __forceinline__ float ex2f(float x) {
    float y; asm("ex2.approx.ftz.f32 %0, %1;" : "=f"(y) : "f"(x)); return y;
}
__device__ __forceinline__ uint32_t h2u(float a, float b) {
    __half2 h = __floats2half2_rn(a, b);
    return *reinterpret_cast<uint32_t*>(&h);
}

// ---------------------------------------------------------------------------
// Kernel 1: per-head QKV projection (fp32 compute, fp16 output).
// grid (BT/64, H, 3), block 256.
// ---------------------------------------------------------------------------
__global__ __launch_bounds__(256) void proj_kernel(
    const float* __restrict__ q, const float* __restrict__ k, const float* __restrict__ v,
    const float* __restrict__ Wq, const float* __restrict__ bq,
    const float* __restrict__ Wk, const float* __restrict__ bk,
    const float* __restrict__ Wv, const float* __restrict__ bv)
{
    __shared__ float At[64*64];
    __shared__ float Wt[64*64];
    __shared__ float bs[64];

    int which = blockIdx.z;
    const float* x    = (which==0) ? q  : (which==1) ? k  : v;
    const float* W    = (which==0) ? Wq : (which==1) ? Wk : Wv;
    const float* bias = (which==0) ? bq : (which==1) ? bk : bv;
    __half* outp      = (which==0) ? g_qh : (which==1) ? g_kh : g_vh;

    int h    = blockIdx.y;
    int row0 = blockIdx.x * 64;
    int t    = threadIdx.x;
    int r    = t & 63, dq = t >> 6;

    {
        const float* xr = x + (size_t)(row0 + r)*DM + h*64 + dq*16;
        #pragma unroll
        for (int u = 0; u < 4; u++) {
            float4 g = *(const float4*)(xr + u*4);
            int d = dq*16 + u*4;
            At[(d+0)*64 + r] = g.x; At[(d+1)*64 + r] = g.y;
            At[(d+2)*64 + r] = g.z; At[(d+3)*64 + r] = g.w;
        }
        const float* wr = W + r*64 + dq*16;
        #pragma unroll
        for (int u = 0; u < 4; u++) {
            float4 g = *(const float4*)(wr + u*4);
            int d = dq*16 + u*4;
            Wt[(d+0)*64 + r] = g.x; Wt[(d+1)*64 + r] = g.y;
            Wt[(d+2)*64 + r] = g.z; Wt[(d+3)*64 + r] = g.w;
        }
        if (t < 64) bs[t] = bias[t];
    }
    __syncthreads();

    int ty = t >> 4, tx = t & 15;
    float acc[4][4] = {};
    #pragma unroll 16
    for (int kk = 0; kk < 64; kk++) {
        float4 a4 = *(const float4*)&At[kk*64 + ty*4];
        float4 b4 = *(const float4*)&Wt[kk*64 + tx*4];
        float av[4] = {a4.x, a4.y, a4.z, a4.w};
        float bv4[4] = {b4.x, b4.y, b4.z, b4.w};
        #pragma unroll
        for (int i = 0; i < 4; i++)
            #pragma unroll
            for (int j = 0; j < 4; j++)
                acc[i][j] += av[i] * bv4[j];
    }

    int b_ = row0 / TT;
    #pragma unroll
    for (int i = 0; i < 4; i++) {
        int row = row0 + ty*4 + i;
        int tok = row - b_*TT;
        __half* po = outp + ((size_t)(b_*HH + h)*TT + tok)*DK + tx*4;
        __half2 h0 = __floats2half2_rn(acc[i][0] + bs[tx*4+0], acc[i][1] + bs[tx*4+1]);
        __half2 h1 = __floats2half2_rn(acc[i][2] + bs[tx*4+2], acc[i][3] + bs[tx*4+3]);
        *(__half2*)(po)     = h0;
        *(__half2*)(po + 2) = h1;
    }
}

// ---------------------------------------------------------------------------
// Kernel 2: flash attention with fp16 mma.sync tensor cores.
// grid (T/128, B*H), block 256 (8 warps x 16 rows = 128 q-rows per block).
// kv tiles of 64. Double-buffered cp.async K/V tiles.
// smem (halfs): Q 128x72, then K/V stages 64x72 each.
// ---------------------------------------------------------------------------
#define LDSH 72      // padded row stride in halfs (144B: 16B-aligned, conflict-free)
#define SM_Q 0
#define SM_KV (128*LDSH)
#define SM_STAGE (2*64*LDSH)
#define SMEM_ATTN ((128*LDSH + 2*2*64*LDSH) * 2)   // bytes = 55296

__global__ __launch_bounds__(256) void attn_kernel()
{
    extern __shared__ __half sh[];
    __half* Qs = sh + SM_Q;

    const int t    = threadIdx.x;
    const int lane = t & 31;
    const int wid  = t >> 5;
    const int wrow = wid * 16;

    const int bh = blockIdx.y;
    const int q0 = blockIdx.x * 128;
    const __half* Qb = g_qh + (size_t)bh*TT*DK;
    const __half* Kb = g_kh + (size_t)bh*TT*DK;
    const __half* Vb = g_vh + (size_t)bh*TT*DK;

    // ---- stage Q tile into smem (128 rows x 64 halfs -> padded) ----
    #pragma unroll
    for (int i = 0; i < 4; i++) {
        int c = t + i*256;           // 1024 chunks of 16B
        int row = c >> 3, off = (c & 7) * 8;
        uint4 val = *(const uint4*)(Qb + (size_t)(q0 + row)*DK + off);
        *(uint4*)(Qs + row*LDSH + off) = val;
    }

    // ---- prefetch kv tile 0 ----
    {
        __half* Ks = sh + SM_KV;               // stage 0
        __half* Vs = Ks + 64*LDSH;
        #pragma unroll
        for (int i = 0; i < 2; i++) {
            int c = t + i*256;                 // 512 chunks per matrix
            int row = c >> 3, off = (c & 7) * 8;
            cp16(Ks + row*LDSH + off, Kb + (size_t)row*DK + off);
            cp16(Vs + row*LDSH + off, Vb + (size_t)row*DK + off);
        }
        cp_commit();
    }
    __syncthreads();

    // ---- load Q fragments (once) ----
    uint32_t qf[4][4];
    {
        int rowl = ((lane >> 3) & 1) * 8 + (lane & 7);
        int coll = (lane >> 4) * 8;
        #pragma unroll
        for (int kb = 0; kb < 4; kb++) {
            uint32_t a = smaddr(Qs + (wrow + rowl)*LDSH + kb*16 + coll);
            ldsm4(qf[kb], a);
        }
    }

    float o[8][4] = {};
    float m0 = -INFINITY, m1 = -INFINITY, l0 = 0.f, l1 = 0.f;
    const float kS = 0.125f * 1.4426950408889634f;   // scale * log2(e)

    const int NT = TT / 64;   // 32 kv tiles
    for (int it = 0; it < NT; it++) {
        int st = it & 1;
        __half* Ks = sh + SM_KV + st*SM_STAGE;
        __half* Vs = Ks + 64*LDSH;

        if (it + 1 < NT) {
            __half* Kn = sh + SM_KV + ((it+1)&1)*SM_STAGE;
            __half* Vn = Kn + 64*LDSH;
            int kvn = (it+1) * 64;
            #pragma unroll
            for (int i = 0; i < 2; i++) {
                int c = t + i*256;
                int row = c >> 3, off = (c & 7) * 8;
                cp16(Kn + row*LDSH + off, Kb + (size_t)(kvn + row)*DK + off);
                cp16(Vn + row*LDSH + off, Vb + (size_t)(kvn + row)*DK + off);
            }
            cp_commit();
            cp_wait<1>();
        } else {
            cp_wait<0>();
        }
        __syncthreads();

        // ---- S = Q K^T : 16x64 per warp ----
        float sc[8][4] = {};
        {
            int rowl = lane & 7;
            int gl   = lane >> 3;
            #pragma unroll
            for (int nb = 0; nb < 8; nb++) {
                #pragma unroll
                for (int p = 0; p < 2; p++) {
                    uint32_t b[4];
                    uint32_t a = smaddr(Ks + (nb*8 + rowl)*LDSH + p*32 + gl*8);
                    ldsm4(b, a);
                    mma16816(sc[nb], qf[2*p+0][0], qf[2*p+0][1], qf[2*p+0][2], qf[2*p+0][3], b[0], b[1]);
                    mma16816(sc[nb], qf[2*p+1][0], qf[2*p+1][1], qf[2*p+1][2], qf[2*p+1][3], b[2], b[3]);
                }
            }
        }

        // ---- online softmax (raw-score domain, base-2) ----
        float mx0 = -INFINITY, mx1 = -INFINITY;
        #pragma unroll
        for (int nb = 0; nb < 8; nb++) {
            mx0 = fmaxf(mx0, fmaxf(sc[nb][0], sc[nb][1]));
            mx1 = fmaxf(mx1, fmaxf(sc[nb][2], sc[nb][3]));
        }
        #pragma unroll
        for (int off = 1; off < 4; off <<= 1) {
            mx0 = fmaxf(mx0, __shfl_xor_sync(0xffffffffu, mx0, off));
            mx1 = fmaxf(mx1, __shfl_xor_sync(0xffffffffu, mx1, off));
        }
        float mn0 = fmaxf(m0, mx0), mn1 = fmaxf(m1, mx1);
        float fac0 = ex2f((m0 - mn0) * kS), fac1 = ex2f((m1 - mn1) * kS);
        m0 = mn0; m1 = mn1;
        float nm0 = m0 * kS, nm1 = m1 * kS;

        uint32_t ph[8][2];
        float ps0 = 0.f, ps1 = 0.f;
        #pragma unroll
        for (int nb = 0; nb < 8; nb++) {
            float e0 = ex2f(fmaf(sc[nb][0], kS, -nm0));
            float e1 = ex2f(fmaf(sc[nb][1], kS, -nm0));
            float e2 = ex2f(fmaf(sc[nb][2], kS, -nm1));
            float e3 = ex2f(fmaf(sc[nb][3], kS, -nm1));
            ps0 += e0 + e1; ps1 += e2 + e3;
            ph[nb][0] = h2u(e0, e1);
            ph[nb][1] = h2u(e2, e3);
        }
        #pragma unroll
        for (int off = 1; off < 4; off <<= 1) {
            ps0 += __shfl_xor_sync(0xffffffffu, ps0, off);
            ps1 += __shfl_xor_sync(0xffffffffu, ps1, off);
        }
        l0 = l0 * fac0 + ps0;
        l1 = l1 * fac1 + ps1;
        #pragma unroll
        for (int db = 0; db < 8; db++) {
            o[db][0] *= fac0; o[db][1] *= fac0;
            o[db][2] *= fac1; o[db][3] *= fac1;
        }

        // ---- O += P @ V ----
        {
            int rowl = lane & 7;
            int gl   = lane >> 3;
            #pragma unroll
            for (int kb2 = 0; kb2 < 4; kb2++) {
                uint32_t a0 = ph[2*kb2][0],   a1 = ph[2*kb2][1];
                uint32_t a2 = ph[2*kb2+1][0], a3 = ph[2*kb2+1][1];
                #pragma unroll
                for (int dbp = 0; dbp < 4; dbp++) {
                    uint32_t b[4];
                    uint32_t ad = smaddr(Vs + (kb2*16 + (gl & 1)*8 + rowl)*LDSH
                                            + dbp*16 + (gl >> 1)*8);
                    ldsm4t(b, ad);
                    mma16816(o[2*dbp+0], a0, a1, a2, a3, b[0], b[1]);
                    mma16816(o[2*dbp+1], a0, a1, a2, a3, b[2], b[3]);
                }
            }
        }
        __syncthreads();
    }

    // ---- normalize + write to concat [B,T,768] fp32 ----
    int b_ = bh / HH, h_ = bh % HH;
    float inv0 = 1.0f / l0, inv1 = 1.0f / l1;
    int r0 = q0 + wrow + (lane >> 2);
    int r1 = r0 + 8;
    int colb = h_*64 + (lane & 3)*2;
    float* base0 = g_cat + (size_t)(b_*TT + r0)*DM + colb;
    float* base1 = g_cat + (size_t)(b_*TT + r1)*DM + colb;
    #pragma unroll
    for (int db = 0; db < 8; db++) {
        *(float2*)(base0 + db*8) = make_float2(o[db][0]*inv0, o[db][1]*inv0);
        *(float2*)(base1 + db*8) = make_float2(o[db][2]*inv1, o[db][3]*inv1);
    }
}

// ---------------------------------------------------------------------------
// Kernel 3: output projection  out = concat @ Wo^T + bo   (fp32)
// ---------------------------------------------------------------------------
__global__ __launch_bounds__(256) void outproj_kernel(
    const float* __restrict__ Wo, const float* __restrict__ bo, float* __restrict__ outp)
{
    __shared__ float At[64*64];
    __shared__ float Btile[64*64];
    int m0 = blockIdx.x * 64, n0 = blockIdx.y * 64;
    int t  = threadIdx.x;
    int r  = t & 63, dq = t >> 6;
    int ty = t >> 4, tx = t & 15;

    float acc[4][4] = {};
    for (int k0 = 0; k0 < DM; k0 += 64) {
        __syncthreads();
        {
            const float* ar = g_cat + (size_t)(n0 + r)*DM + k0 + dq*16;
            #pragma unroll
            for (int u = 0; u < 4; u++) {
                float4 g = *(const float4*)(ar + u*4);
                int d = dq*16 + u*4;
                At[(d+0)*64 + r] = g.x; At[(d+1)*64 + r] = g.y;
                At[(d+2)*64 + r] = g.z; At[(d+3)*64 + r] = g.w;
            }
            const float* br = Wo + (size_t)(m0 + r)*DM + k0 + dq*16;
            #pragma unroll
            for (int u = 0; u < 4; u++) {
                float4 g = *(const float4*)(br + u*4);
                int d = dq*16 + u*4;
                Btile[(d+0)*64 + r] = g.x; Btile[(d+1)*64 + r] = g.y;
                Btile[(d+2)*64 + r] = g.z; Btile[(d+3)*64 + r] = g.w;
            }
        }
        __syncthreads();
        #pragma unroll 16
        for (int kk = 0; kk < 64; kk++) {
            float4 a4 = *(const float4*)&At[kk*64 + ty*4];
            float4 b4 = *(const float4*)&Btile[kk*64 + tx*4];
            float av[4] = {a4.x, a4.y, a4.z, a4.w};
            float bv4[4] = {b4.x, b4.y, b4.z, b4.w};
            #pragma unroll
            for (int i = 0; i < 4; i++)
                #pragma unroll
                for (int j = 0; j < 4; j++)
                    acc[i][j] += av[i] * bv4[j];
        }
    }

    #pragma unroll
    for (int i = 0; i < 4; i++) {
        int n = n0 + ty*4 + i;
        float4 o4;
        o4.x = acc[i][0] + bo[m0 + tx*4 + 0];
        o4.y = acc[i][1] + bo[m0 + tx*4 + 1];
        o4.z = acc[i][2] + bo[m0 + tx*4 + 2];
        o4.w = acc[i][3] + bo[m0 + tx*4 + 3];
        *(float4*)(outp + (size_t)n*DM + m0 + tx*4) = o4;
    }
}

// ---------------------------------------------------------------------------
extern "C" void kernel_launch(void* const* d_in, const int* in_sizes, int n_in,
                              void* d_out, int out_size)
{
    const float* q  = (const float*)d_in[0];
    const float* k  = (const float*)d_in[1];
    const float* v  = (const float*)d_in[2];
    const float* Wq = (const float*)d_in[3];
    const float* bq = (const float*)d_in[4];
    const float* Wk = (const float*)d_in[5];
    const float* bk = (const float*)d_in[6];
    const float* Wv = (const float*)d_in[7];
    const float* bv = (const float*)d_in[8];
    const float* Wo = (const float*)d_in[9];
    const float* bo = (const float*)d_in[10];
    float* outp = (float*)d_out;

    cudaFuncSetAttribute(attn_kernel, cudaFuncAttributeMaxDynamicSharedMemorySize, SMEM_ATTN);

    proj_kernel<<<dim3(BT/64, HH, 3), 256>>>(q, k, v, Wq, bq, Wk, bk, Wv, bv);
    attn_kernel<<<dim3(TT/128, BB*HH), 256, SMEM_ATTN>>>();
    outproj_kernel<<<dim3(DM/64, BT/64), 256>>>(Wo, bo, outp);
}

// round 5
// speedup vs baseline: 11.0851x; 1.8905x over previous
#include <cuda_runtime.h>
#include <cuda_fp16.h>
#include <math.h>
#include <stdint.h>

#define BB 4
#define TT 2048
#define HH 12
#define DK 64
#define DM 768
#define BT (BB*TT)

// Scratch (device globals — no allocations allowed)
__device__ __half g_qh[(size_t)BB*HH*TT*DK];   // [B*H, T, 64] fp16
__device__ __half g_kh[(size_t)BB*HH*TT*DK];
__device__ __half g_vh[(size_t)BB*HH*TT*DK];
__device__ __half g_cat[(size_t)BT*DM];        // [B,T,768] fp16
__device__ __half g_woh[(size_t)DM*DM];        // Wo fp16

// ---------------------------------------------------------------------------
// helpers
// ---------------------------------------------------------------------------
__device__ __forceinline__ uint32_t smaddr(const void* p) {
    return (uint32_t)__cvta_generic_to_shared(p);
}
__device__ __forceinline__ void ldsm4(uint32_t* r, uint32_t a) {
    asm volatile("ldmatrix.sync.aligned.m8n8.x4.shared.b16 {%0,%1,%2,%3}, [%4];"
                 : "=r"(r[0]), "=r"(r[1]), "=r"(r[2]), "=r"(r[3]) : "r"(a));
}
__device__ __forceinline__ void ldsm4t(uint32_t* r, uint32_t a) {
    asm volatile("ldmatrix.sync.aligned.m8n8.x4.trans.shared.b16 {%0,%1,%2,%3}, [%4];"
                 : "=r"(r[0]), "=r"(r[1]), "=r"(r[2]), "=r"(r[3]) : "r"(a));
}
__device__ __forceinline__ void mma16816(float* c,
    uint32_t a0, uint32_t a1, uint32_t a2, uint32_t a3, uint32_t b0, uint32_t b1) {
    asm volatile(
        "mma.sync.aligned.m16n8k16.row.col.f32.f16.f16.f32 "
        "{%0,%1,%2,%3}, {%4,%5,%6,%7}, {%8,%9}, {%0,%1,%2,%3};"
        : "+f"(c[0]), "+f"(c[1]), "+f"(c[2]), "+f"(c[3])
        : "r"(a0), "r"(a1), "r"(a2), "r"(a3), "r"(b0), "r"(b1));
}
__device__ __forceinline__ void cp16(void* dst, const void* src) {
    uint32_t d = smaddr(dst);
    asm volatile("cp.async.cg.shared.global [%0], [%1], 16;" :: "r"(d), "l"(src) : "memory");
}
__device__ __forceinline__ void cp_commit() {
    asm volatile("cp.async.commit_group;" ::: "memory");
}
template<int N> __device__ __forceinline__ void cp_wait() {
    asm volatile("cp.async.wait_group %0;" :: "n"(N) : "memory");
}
__device__ __forceinline__ float ex2f(float x) {
    float y; asm("ex2.approx.ftz.f32 %0, %1;" : "=f"(y) : "f"(x)); return y;
}
__device__ __forceinline__ uint32_t h2u(float a, float b) {
    __half2 h = __floats2half2_rn(a, b);
    return *reinterpret_cast<uint32_t*>(&h);
}

// ---------------------------------------------------------------------------
// Kernel 0: convert Wo to fp16
// ---------------------------------------------------------------------------
__global__ __launch_bounds__(256) void convert_wo_kernel(const float* __restrict__ Wo)
{
    int i = blockIdx.x * 256 + threadIdx.x;     // 147456 float4 chunks
    float4 w = ((const float4*)Wo)[i];
    __half2 a = __floats2half2_rn(w.x, w.y);
    __half2 b = __floats2half2_rn(w.z, w.w);
    uint2 pk;
    pk.x = *reinterpret_cast<uint32_t*>(&a);
    pk.y = *reinterpret_cast<uint32_t*>(&b);
    ((uint2*)g_woh)[i] = pk;
}

// ---------------------------------------------------------------------------
// Kernel 1: per-head QKV projection (fp32 compute, fp16 output).
// grid (BT/64, H, 3), block 256.
// ---------------------------------------------------------------------------
__global__ __launch_bounds__(256) void proj_kernel(
    const float* __restrict__ q, const float* __restrict__ k, const float* __restrict__ v,
    const float* __restrict__ Wq, const float* __restrict__ bq,
    const float* __restrict__ Wk, const float* __restrict__ bk,
    const float* __restrict__ Wv, const float* __restrict__ bv)
{
    __shared__ float At[64*64];
    __shared__ float Wt[64*64];
    __shared__ float bs[64];

    int which = blockIdx.z;
    const float* x    = (which==0) ? q  : (which==1) ? k  : v;
    const float* W    = (which==0) ? Wq : (which==1) ? Wk : Wv;
    const float* bias = (which==0) ? bq : (which==1) ? bk : bv;
    __half* outp      = (which==0) ? g_qh : (which==1) ? g_kh : g_vh;

    int h    = blockIdx.y;
    int row0 = blockIdx.x * 64;
    int t    = threadIdx.x;
    int r    = t & 63, dq = t >> 6;

    {
        const float* xr = x + (size_t)(row0 + r)*DM + h*64 + dq*16;
        #pragma unroll
        for (int u = 0; u < 4; u++) {
            float4 g = *(const float4*)(xr + u*4);
            int d = dq*16 + u*4;
            At[(d+0)*64 + r] = g.x; At[(d+1)*64 + r] = g.y;
            At[(d+2)*64 + r] = g.z; At[(d+3)*64 + r] = g.w;
        }
        const float* wr = W + r*64 + dq*16;
        #pragma unroll
        for (int u = 0; u < 4; u++) {
            float4 g = *(const float4*)(wr + u*4);
            int d = dq*16 + u*4;
            Wt[(d+0)*64 + r] = g.x; Wt[(d+1)*64 + r] = g.y;
            Wt[(d+2)*64 + r] = g.z; Wt[(d+3)*64 + r] = g.w;
        }
        if (t < 64) bs[t] = bias[t];
    }
    __syncthreads();

    int ty = t >> 4, tx = t & 15;
    float acc[4][4] = {};
    #pragma unroll 16
    for (int kk = 0; kk < 64; kk++) {
        float4 a4 = *(const float4*)&At[kk*64 + ty*4];
        float4 b4 = *(const float4*)&Wt[kk*64 + tx*4];
        float av[4] = {a4.x, a4.y, a4.z, a4.w};
        float bv4[4] = {b4.x, b4.y, b4.z, b4.w};
        #pragma unroll
        for (int i = 0; i < 4; i++)
            #pragma unroll
            for (int j = 0; j < 4; j++)
                acc[i][j] += av[i] * bv4[j];
    }

    int b_ = row0 / TT;
    #pragma unroll
    for (int i = 0; i < 4; i++) {
        int row = row0 + ty*4 + i;
        int tok = row - b_*TT;
        __half* po = outp + ((size_t)(b_*HH + h)*TT + tok)*DK + tx*4;
        __half2 h0 = __floats2half2_rn(acc[i][0] + bs[tx*4+0], acc[i][1] + bs[tx*4+1]);
        __half2 h1 = __floats2half2_rn(acc[i][2] + bs[tx*4+2], acc[i][3] + bs[tx*4+3]);
        *(__half2*)(po)     = h0;
        *(__half2*)(po + 2) = h1;
    }
}

// ---------------------------------------------------------------------------
// Kernel 2: flash attention with fp16 mma.sync tensor cores.
// grid (T/128, B*H), block 256 (8 warps x 16 rows = 128 q-rows per block).
// ---------------------------------------------------------------------------
#define LDSH 72      // padded row stride in halfs (144B)
#define SM_Q 0
#define SM_KV (128*LDSH)
#define SM_STAGE (2*64*LDSH)
#define SMEM_ATTN ((128*LDSH + 2*2*64*LDSH) * 2)   // bytes = 55296

__global__ __launch_bounds__(256) void attn_kernel()
{
    extern __shared__ __half sh[];
    __half* Qs = sh + SM_Q;

    const int t    = threadIdx.x;
    const int lane = t & 31;
    const int wid  = t >> 5;
    const int wrow = wid * 16;

    const int bh = blockIdx.y;
    const int q0 = blockIdx.x * 128;
    const __half* Qb = g_qh + (size_t)bh*TT*DK;
    const __half* Kb = g_kh + (size_t)bh*TT*DK;
    const __half* Vb = g_vh + (size_t)bh*TT*DK;

    #pragma unroll
    for (int i = 0; i < 4; i++) {
        int c = t + i*256;
        int row = c >> 3, off = (c & 7) * 8;
        uint4 val = *(const uint4*)(Qb + (size_t)(q0 + row)*DK + off);
        *(uint4*)(Qs + row*LDSH + off) = val;
    }

    {
        __half* Ks = sh + SM_KV;
        __half* Vs = Ks + 64*LDSH;
        #pragma unroll
        for (int i = 0; i < 2; i++) {
            int c = t + i*256;
            int row = c >> 3, off = (c & 7) * 8;
            cp16(Ks + row*LDSH + off, Kb + (size_t)row*DK + off);
            cp16(Vs + row*LDSH + off, Vb + (size_t)row*DK + off);
        }
        cp_commit();
    }
    __syncthreads();

    uint32_t qf[4][4];
    {
        int rowl = ((lane >> 3) & 1) * 8 + (lane & 7);
        int coll = (lane >> 4) * 8;
        #pragma unroll
        for (int kb = 0; kb < 4; kb++) {
            uint32_t a = smaddr(Qs + (wrow + rowl)*LDSH + kb*16 + coll);
            ldsm4(qf[kb], a);
        }
    }

    float o[8][4] = {};
    float m0 = -INFINITY, m1 = -INFINITY, l0 = 0.f, l1 = 0.f;
    const float kS = 0.125f * 1.4426950408889634f;

    const int NT = TT / 64;
    for (int it = 0; it < NT; it++) {
        int st = it & 1;
        __half* Ks = sh + SM_KV + st*SM_STAGE;
        __half* Vs = Ks + 64*LDSH;

        if (it + 1 < NT) {
            __half* Kn = sh + SM_KV + ((it+1)&1)*SM_STAGE;
            __half* Vn = Kn + 64*LDSH;
            int kvn = (it+1) * 64;
            #pragma unroll
            for (int i = 0; i < 2; i++) {
                int c = t + i*256;
                int row = c >> 3, off = (c & 7) * 8;
                cp16(Kn + row*LDSH + off, Kb + (size_t)(kvn + row)*DK + off);
                cp16(Vn + row*LDSH + off, Vb + (size_t)(kvn + row)*DK + off);
            }
            cp_commit();
            cp_wait<1>();
        } else {
            cp_wait<0>();
        }
        __syncthreads();

        float sc[8][4] = {};
        {
            int rowl = lane & 7;
            int gl   = lane >> 3;
            #pragma unroll
            for (int nb = 0; nb < 8; nb++) {
                #pragma unroll
                for (int p = 0; p < 2; p++) {
                    uint32_t b[4];
                    uint32_t a = smaddr(Ks + (nb*8 + rowl)*LDSH + p*32 + gl*8);
                    ldsm4(b, a);
                    mma16816(sc[nb], qf[2*p+0][0], qf[2*p+0][1], qf[2*p+0][2], qf[2*p+0][3], b[0], b[1]);
                    mma16816(sc[nb], qf[2*p+1][0], qf[2*p+1][1], qf[2*p+1][2], qf[2*p+1][3], b[2], b[3]);
                }
            }
        }

        float mx0 = -INFINITY, mx1 = -INFINITY;
        #pragma unroll
        for (int nb = 0; nb < 8; nb++) {
            mx0 = fmaxf(mx0, fmaxf(sc[nb][0], sc[nb][1]));
            mx1 = fmaxf(mx1, fmaxf(sc[nb][2], sc[nb][3]));
        }
        #pragma unroll
        for (int off = 1; off < 4; off <<= 1) {
            mx0 = fmaxf(mx0, __shfl_xor_sync(0xffffffffu, mx0, off));
            mx1 = fmaxf(mx1, __shfl_xor_sync(0xffffffffu, mx1, off));
        }
        float mn0 = fmaxf(m0, mx0), mn1 = fmaxf(m1, mx1);
        float fac0 = ex2f((m0 - mn0) * kS), fac1 = ex2f((m1 - mn1) * kS);
        m0 = mn0; m1 = mn1;
        float nm0 = m0 * kS, nm1 = m1 * kS;

        uint32_t ph[8][2];
        float ps0 = 0.f, ps1 = 0.f;
        #pragma unroll
        for (int nb = 0; nb < 8; nb++) {
            float e0 = ex2f(fmaf(sc[nb][0], kS, -nm0));
            float e1 = ex2f(fmaf(sc[nb][1], kS, -nm0));
            float e2 = ex2f(fmaf(sc[nb][2], kS, -nm1));
            float e3 = ex2f(fmaf(sc[nb][3], kS, -nm1));
            ps0 += e0 + e1; ps1 += e2 + e3;
            ph[nb][0] = h2u(e0, e1);
            ph[nb][1] = h2u(e2, e3);
        }
        #pragma unroll
        for (int off = 1; off < 4; off <<= 1) {
            ps0 += __shfl_xor_sync(0xffffffffu, ps0, off);
            ps1 += __shfl_xor_sync(0xffffffffu, ps1, off);
        }
        l0 = l0 * fac0 + ps0;
        l1 = l1 * fac1 + ps1;
        #pragma unroll
        for (int db = 0; db < 8; db++) {
            o[db][0] *= fac0; o[db][1] *= fac0;
            o[db][2] *= fac1; o[db][3] *= fac1;
        }

        {
            int rowl = lane & 7;
            int gl   = lane >> 3;
            #pragma unroll
            for (int kb2 = 0; kb2 < 4; kb2++) {
                uint32_t a0 = ph[2*kb2][0],   a1 = ph[2*kb2][1];
                uint32_t a2 = ph[2*kb2+1][0], a3 = ph[2*kb2+1][1];
                #pragma unroll
                for (int dbp = 0; dbp < 4; dbp++) {
                    uint32_t b[4];
                    uint32_t ad = smaddr(Vs + (kb2*16 + (gl & 1)*8 + rowl)*LDSH
                                            + dbp*16 + (gl >> 1)*8);
                    ldsm4t(b, ad);
                    mma16816(o[2*dbp+0], a0, a1, a2, a3, b[0], b[1]);
                    mma16816(o[2*dbp+1], a0, a1, a2, a3, b[2], b[3]);
                }
            }
        }
        __syncthreads();
    }

    // ---- normalize + write to concat [B,T,768] fp16 ----
    int b_ = bh / HH, h_ = bh % HH;
    float inv0 = 1.0f / l0, inv1 = 1.0f / l1;
    int r0 = q0 + wrow + (lane >> 2);
    int r1 = r0 + 8;
    int colb = h_*64 + (lane & 3)*2;
    __half* base0 = g_cat + (size_t)(b_*TT + r0)*DM + colb;
    __half* base1 = g_cat + (size_t)(b_*TT + r1)*DM + colb;
    #pragma unroll
    for (int db = 0; db < 8; db++) {
        *(__half2*)(base0 + db*8) = __floats2half2_rn(o[db][0]*inv0, o[db][1]*inv0);
        *(__half2*)(base1 + db*8) = __floats2half2_rn(o[db][2]*inv1, o[db][3]*inv1);
    }
}

// ---------------------------------------------------------------------------
// Kernel 3: output projection with fp16 mma: out = cat @ Wo^T + bo
// grid (DM/128, BT/128), block 256 (8 warps). 128x128 C tile, k=768 in 12
// chunks of 64, double-buffered cp.async.
// ---------------------------------------------------------------------------
#define OP_LDSH 72
#define OP_MAT  (128*OP_LDSH)                 // halfs per matrix buffer
#define SMEM_OP (4*OP_MAT*2)                  // bytes = 73728

__global__ __launch_bounds__(256) void outproj_kernel(
    const float* __restrict__ bo, float* __restrict__ outp)
{
    extern __shared__ __half sm2[];
    const int t    = threadIdx.x;
    const int lane = t & 31;
    const int wid  = t >> 5;
    const int wrow = wid * 16;
    const int m0 = blockIdx.x * 128;
    const int n0 = blockIdx.y * 128;

    // prefetch chunk 0
    {
        __half* As = sm2;
        __half* Bs = As + OP_MAT;
        #pragma unroll
        for (int i = 0; i < 4; i++) {
            int c = t + i*256;                 // 1024 chunks of 16B
            int row = c >> 3, off = (c & 7) * 8;
            cp16(As + row*OP_LDSH + off, g_cat + (size_t)(n0 + row)*DM + off);
            cp16(Bs + row*OP_LDSH + off, g_woh + (size_t)(m0 + row)*DM + off);
        }
        cp_commit();
    }

    float c[16][4] = {};
    const int NC = DM / 64;   // 12
    for (int it = 0; it < NC; it++) {
        int st = it & 1;
        __half* As = sm2 + st*2*OP_MAT;
        __half* Bs = As + OP_MAT;

        if (it + 1 < NC) {
            int k0 = (it+1) * 64;
            __half* An = sm2 + ((it+1)&1)*2*OP_MAT;
            __half* Bn = An + OP_MAT;
            #pragma unroll
            for (int i = 0; i < 4; i++) {
                int cc = t + i*256;
                int row = cc >> 3, off = (cc & 7) * 8;
                cp16(An + row*OP_LDSH + off, g_cat + (size_t)(n0 + row)*DM + k0 + off);
                cp16(Bn + row*OP_LDSH + off, g_woh + (size_t)(m0 + row)*DM + k0 + off);
            }
            cp_commit();
            cp_wait<1>();
        } else {
            cp_wait<0>();
        }
        __syncthreads();

        // A fragments: 16 rows x 64 k
        uint32_t af[4][4];
        {
            int rowl = ((lane >> 3) & 1) * 8 + (lane & 7);
            int coll = (lane >> 4) * 8;
            #pragma unroll
            for (int kb = 0; kb < 4; kb++) {
                uint32_t a = smaddr(As + (wrow + rowl)*OP_LDSH + kb*16 + coll);
                ldsm4(af[kb], a);
            }
        }

        // C += A @ B^T for 128 cols
        {
            int rowb = lane & 7;
            int gl   = lane >> 3;
            #pragma unroll
            for (int nb = 0; nb < 16; nb++) {
                #pragma unroll
                for (int p = 0; p < 2; p++) {
                    uint32_t b[4];
                    uint32_t a = smaddr(Bs + (nb*8 + rowb)*OP_LDSH + p*32 + gl*8);
                    ldsm4(b, a);
                    mma16816(c[nb], af[2*p+0][0], af[2*p+0][1], af[2*p+0][2], af[2*p+0][3], b[0], b[1]);
                    mma16816(c[nb], af[2*p+1][0], af[2*p+1][1], af[2*p+1][2], af[2*p+1][3], b[2], b[3]);
                }
            }
        }
        __syncthreads();
    }

    // epilogue: add bias, write fp32
    int r0 = n0 + wrow + (lane >> 2);
    int r1 = r0 + 8;
    #pragma unroll
    for (int nb = 0; nb < 16; nb++) {
        int col = m0 + nb*8 + (lane & 3)*2;
        float b0 = bo[col], b1 = bo[col + 1];
        *(float2*)(outp + (size_t)r0*DM + col) = make_float2(c[nb][0] + b0, c[nb][1] + b1);
        *(float2*)(outp + (size_t)r1*DM + col) = make_float2(c[nb][2] + b0, c[nb][3] + b1);
    }
}

// ---------------------------------------------------------------------------
extern "C" void kernel_launch(void* const* d_in, const int* in_sizes, int n_in,
                              void* d_out, int out_size)
{
    const float* q  = (const float*)d_in[0];
    const float* k  = (const float*)d_in[1];
    const float* v  = (const float*)d_in[2];
    const float* Wq = (const float*)d_in[3];
    const float* bq = (const float*)d_in[4];
    const float* Wk = (const float*)d_in[5];
    const float* bk = (const float*)d_in[6];
    const float* Wv = (const float*)d_in[7];
    const float* bv = (const float*)d_in[8];
    const float* Wo = (const float*)d_in[9];
    const float* bo = (const float*)d_in[10];
    float* outp = (float*)d_out;

    cudaFuncSetAttribute(attn_kernel, cudaFuncAttributeMaxDynamicSharedMemorySize, SMEM_ATTN);
    cudaFuncSetAttribute(outproj_kernel, cudaFuncAttributeMaxDynamicSharedMemorySize, SMEM_OP);

    convert_wo_kernel<<<DM*DM/4/256, 256>>>(Wo);
    proj_kernel<<<dim3(BT/64, HH, 3), 256>>>(q, k, v, Wq, bq, Wk, bk, Wv, bv);
    attn_kernel<<<dim3(TT/128, BB*HH), 256, SMEM_ATTN>>>();
    outproj_kernel<<<dim3(DM/128, BT/128), 256, SMEM_OP>>>(bo, outp);
}

// round 6
// speedup vs baseline: 13.3949x; 1.2084x over previous
#include <cuda_runtime.h>
#include <cuda_fp16.h>
#include <math.h>
#include <stdint.h>

#define BB 4
#define TT 2048
#define HH 12
#define DK 64
#define DM 768
#define BT (BB*TT)

// Scratch (device globals — no allocations allowed)
__device__ __half g_qh[(size_t)BB*HH*TT*DK];   // [B*H, T, 64] fp16
__device__ __half g_kh[(size_t)BB*HH*TT*DK];
__device__ __half g_vh[(size_t)BB*HH*TT*DK];
__device__ __half g_cat[(size_t)BT*DM];        // [B,T,768] fp16
__device__ __half g_woh[(size_t)DM*DM];        // Wo fp16

// ---------------------------------------------------------------------------
// helpers
// ---------------------------------------------------------------------------
__device__ __forceinline__ uint32_t smaddr(const void* p) {
    return (uint32_t)__cvta_generic_to_shared(p);
}
__device__ __forceinline__ void ldsm4(uint32_t* r, uint32_t a) {
    asm volatile("ldmatrix.sync.aligned.m8n8.x4.shared.b16 {%0,%1,%2,%3}, [%4];"
                 : "=r"(r[0]), "=r"(r[1]), "=r"(r[2]), "=r"(r[3]) : "r"(a));
}
__device__ __forceinline__ void ldsm4t(uint32_t* r, uint32_t a) {
    asm volatile("ldmatrix.sync.aligned.m8n8.x4.trans.shared.b16 {%0,%1,%2,%3}, [%4];"
                 : "=r"(r[0]), "=r"(r[1]), "=r"(r[2]), "=r"(r[3]) : "r"(a));
}
__device__ __forceinline__ void mma16816(float* c,
    uint32_t a0, uint32_t a1, uint32_t a2, uint32_t a3, uint32_t b0, uint32_t b1) {
    asm volatile(
        "mma.sync.aligned.m16n8k16.row.col.f32.f16.f16.f32 "
        "{%0,%1,%2,%3}, {%4,%5,%6,%7}, {%8,%9}, {%0,%1,%2,%3};"
        : "+f"(c[0]), "+f"(c[1]), "+f"(c[2]), "+f"(c[3])
        : "r"(a0), "r"(a1), "r"(a2), "r"(a3), "r"(b0), "r"(b1));
}
__device__ __forceinline__ void cp16(void* dst, const void* src) {
    uint32_t d = smaddr(dst);
    asm volatile("cp.async.cg.shared.global [%0], [%1], 16;" :: "r"(d), "l"(src) : "memory");
}
__device__ __forceinline__ void cp_commit() {
    asm volatile("cp.async.commit_group;" ::: "memory");
}
template<int N> __device__ __forceinline__ void cp_wait() {
    asm volatile("cp.async.wait_group %0;" :: "n"(N) : "memory");
}
__device__ __forceinline__ float ex2f(float x) {
    float y; asm("ex2.approx.ftz.f32 %0, %1;" : "=f"(y) : "f"(x)); return y;
}
__device__ __forceinline__ uint32_t h2u(float a, float b) {
    __half2 h = __floats2half2_rn(a, b);
    return *reinterpret_cast<uint32_t*>(&h);
}

// ---------------------------------------------------------------------------
// Kernel 0: convert Wo to fp16
// ---------------------------------------------------------------------------
__global__ __launch_bounds__(256) void convert_wo_kernel(const float* __restrict__ Wo)
{
    int i = blockIdx.x * 256 + threadIdx.x;
    float4 w = ((const float4*)Wo)[i];
    __half2 a = __floats2half2_rn(w.x, w.y);
    __half2 b = __floats2half2_rn(w.z, w.w);
    uint2 pk;
    pk.x = *reinterpret_cast<uint32_t*>(&a);
    pk.y = *reinterpret_cast<uint32_t*>(&b);
    ((uint2*)g_woh)[i] = pk;
}

// ---------------------------------------------------------------------------
// Kernel 1: QKV projection as one [BT*H, 64] @ [64,64]^T fp16 GEMM.
// grid (768, 1, 3), block 256 (8 warps x 16 rows = 128 rows/block).
// x viewed as [(B*T*H), 64] row-major (contiguous); epilogue scatters to
// [B*H, T, 64]. fp32->fp16 conversion inline on load.
// ---------------------------------------------------------------------------
#define PJ_LDSH 72

__global__ __launch_bounds__(256) void proj_kernel(
    const float* __restrict__ q, const float* __restrict__ k, const float* __restrict__ v,
    const float* __restrict__ Wq, const float* __restrict__ bq,
    const float* __restrict__ Wk, const float* __restrict__ bk,
    const float* __restrict__ Wv, const float* __restrict__ bv)
{
    __shared__ __half Xs[128*PJ_LDSH];
    __shared__ __half Ws[64*PJ_LDSH];
    __shared__ float  bs[64];

    int which = blockIdx.z;
    const float* x    = (which==0) ? q  : (which==1) ? k  : v;
    const float* W    = (which==0) ? Wq : (which==1) ? Wk : Wv;
    const float* bias = (which==0) ? bq : (which==1) ? bk : bv;
    __half* outp      = (which==0) ? g_qh : (which==1) ? g_kh : g_vh;

    const int t    = threadIdx.x;
    const int lane = t & 31;
    const int wid  = t >> 5;
    const int wrow = wid * 16;
    const int n0   = blockIdx.x * 128;      // row in the flattened [98304,64] view

    // ---- load X tile (128 rows x 64 fp32 -> fp16 smem) ----
    // 128 rows * 16 float4/row = 2048 chunks; 8 per thread
    const float* xbase = x + (size_t)n0 * 64;
    #pragma unroll
    for (int i = 0; i < 8; i++) {
        int c = t + i*256;
        int row = c >> 4, off = (c & 15) * 4;
        float4 g = *(const float4*)(xbase + row*64 + off);
        __half2 h0 = __floats2half2_rn(g.x, g.y);
        __half2 h1 = __floats2half2_rn(g.z, g.w);
        uint2 pk;
        pk.x = *reinterpret_cast<uint32_t*>(&h0);
        pk.y = *reinterpret_cast<uint32_t*>(&h1);
        *(uint2*)(Xs + row*PJ_LDSH + off) = pk;
    }
    // ---- load W (64x64 fp32 -> fp16 smem), 1024 chunks, 4 per thread ----
    #pragma unroll
    for (int i = 0; i < 4; i++) {
        int c = t + i*256;
        int row = c >> 4, off = (c & 15) * 4;
        float4 g = *(const float4*)(W + row*64 + off);
        __half2 h0 = __floats2half2_rn(g.x, g.y);
        __half2 h1 = __floats2half2_rn(g.z, g.w);
        uint2 pk;
        pk.x = *reinterpret_cast<uint32_t*>(&h0);
        pk.y = *reinterpret_cast<uint32_t*>(&h1);
        *(uint2*)(Ws + row*PJ_LDSH + off) = pk;
    }
    if (t < 64) bs[t] = bias[t];
    __syncthreads();

    // ---- A fragments (16 rows x k=64) ----
    uint32_t af[4][4];
    {
        int rowl = ((lane >> 3) & 1) * 8 + (lane & 7);
        int coll = (lane >> 4) * 8;
        #pragma unroll
        for (int kb = 0; kb < 4; kb++) {
            uint32_t a = smaddr(Xs + (wrow + rowl)*PJ_LDSH + kb*16 + coll);
            ldsm4(af[kb], a);
        }
    }

    // ---- C = A @ W^T (16x64 per warp) ----
    float c[8][4] = {};
    {
        int rowb = lane & 7;
        int gl   = lane >> 3;
        #pragma unroll
        for (int nb = 0; nb < 8; nb++) {
            #pragma unroll
            for (int p = 0; p < 2; p++) {
                uint32_t b[4];
                uint32_t a = smaddr(Ws + (nb*8 + rowb)*PJ_LDSH + p*32 + gl*8);
                ldsm4(b, a);
                mma16816(c[nb], af[2*p+0][0], af[2*p+0][1], af[2*p+0][2], af[2*p+0][3], b[0], b[1]);
                mma16816(c[nb], af[2*p+1][0], af[2*p+1][1], af[2*p+1][2], af[2*p+1][3], b[2], b[3]);
            }
        }
    }

    // ---- epilogue: bias + scatter to [B*H, T, 64] fp16 ----
    int n_0 = n0 + wrow + (lane >> 2);     // flattened row for c[.][0..1]
    int n_1 = n_0 + 8;
    // n -> (bt, h): h = n % 12, bt = n / 12 ; out row = (b*HH+h)*TT + t
    int bt0 = n_0 / HH, h0_ = n_0 - bt0*HH;
    int bt1 = n_1 / HH, h1_ = n_1 - bt1*HH;
    int b0_ = bt0 / TT, tk0 = bt0 - b0_*TT;
    int b1_ = bt1 / TT, tk1 = bt1 - b1_*TT;
    __half* p0 = outp + ((size_t)(b0_*HH + h0_)*TT + tk0)*DK;
    __half* p1 = outp + ((size_t)(b1_*HH + h1_)*TT + tk1)*DK;
    #pragma unroll
    for (int nb = 0; nb < 8; nb++) {
        int col = nb*8 + (lane & 3)*2;
        float bb0 = bs[col], bb1 = bs[col+1];
        *(__half2*)(p0 + col) = __floats2half2_rn(c[nb][0] + bb0, c[nb][1] + bb1);
        *(__half2*)(p1 + col) = __floats2half2_rn(c[nb][2] + bb0, c[nb][3] + bb1);
    }
}

// ---------------------------------------------------------------------------
// Kernel 2: flash attention with fp16 mma.sync tensor cores.
// grid (T/128, B*H), block 256 (8 warps x 16 rows = 128 q-rows per block).
// ---------------------------------------------------------------------------
#define LDSH 72      // padded row stride in halfs (144B)
#define SM_Q 0
#define SM_KV (128*LDSH)
#define SM_STAGE (2*64*LDSH)
#define SMEM_ATTN ((128*LDSH + 2*2*64*LDSH) * 2)   // bytes = 55296

__global__ __launch_bounds__(256) void attn_kernel()
{
    extern __shared__ __half sh[];
    __half* Qs = sh + SM_Q;

    const int t    = threadIdx.x;
    const int lane = t & 31;
    const int wid  = t >> 5;
    const int wrow = wid * 16;

    const int bh = blockIdx.y;
    const int q0 = blockIdx.x * 128;
    const __half* Qb = g_qh + (size_t)bh*TT*DK;
    const __half* Kb = g_kh + (size_t)bh*TT*DK;
    const __half* Vb = g_vh + (size_t)bh*TT*DK;

    #pragma unroll
    for (int i = 0; i < 4; i++) {
        int c = t + i*256;
        int row = c >> 3, off = (c & 7) * 8;
        uint4 val = *(const uint4*)(Qb + (size_t)(q0 + row)*DK + off);
        *(uint4*)(Qs + row*LDSH + off) = val;
    }

    {
        __half* Ks = sh + SM_KV;
        __half* Vs = Ks + 64*LDSH;
        #pragma unroll
        for (int i = 0; i < 2; i++) {
            int c = t + i*256;
            int row = c >> 3, off = (c & 7) * 8;
            cp16(Ks + row*LDSH + off, Kb + (size_t)row*DK + off);
            cp16(Vs + row*LDSH + off, Vb + (size_t)row*DK + off);
        }
        cp_commit();
    }
    __syncthreads();

    uint32_t qf[4][4];
    {
        int rowl = ((lane >> 3) & 1) * 8 + (lane & 7);
        int coll = (lane >> 4) * 8;
        #pragma unroll
        for (int kb = 0; kb < 4; kb++) {
            uint32_t a = smaddr(Qs + (wrow + rowl)*LDSH + kb*16 + coll);
            ldsm4(qf[kb], a);
        }
    }

    float o[8][4] = {};
    float m0 = -INFINITY, m1 = -INFINITY, l0 = 0.f, l1 = 0.f;
    const float kS = 0.125f * 1.4426950408889634f;

    const int NT = TT / 64;
    for (int it = 0; it < NT; it++) {
        int st = it & 1;
        __half* Ks = sh + SM_KV + st*SM_STAGE;
        __half* Vs = Ks + 64*LDSH;

        if (it + 1 < NT) {
            __half* Kn = sh + SM_KV + ((it+1)&1)*SM_STAGE;
            __half* Vn = Kn + 64*LDSH;
            int kvn = (it+1) * 64;
            #pragma unroll
            for (int i = 0; i < 2; i++) {
                int c = t + i*256;
                int row = c >> 3, off = (c & 7) * 8;
                cp16(Kn + row*LDSH + off, Kb + (size_t)(kvn + row)*DK + off);
                cp16(Vn + row*LDSH + off, Vb + (size_t)(kvn + row)*DK + off);
            }
            cp_commit();
            cp_wait<1>();
        } else {
            cp_wait<0>();
        }
        __syncthreads();

        float sc[8][4] = {};
        {
            int rowl = lane & 7;
            int gl   = lane >> 3;
            #pragma unroll
            for (int nb = 0; nb < 8; nb++) {
                #pragma unroll
                for (int p = 0; p < 2; p++) {
                    uint32_t b[4];
                    uint32_t a = smaddr(Ks + (nb*8 + rowl)*LDSH + p*32 + gl*8);
                    ldsm4(b, a);
                    mma16816(sc[nb], qf[2*p+0][0], qf[2*p+0][1], qf[2*p+0][2], qf[2*p+0][3], b[0], b[1]);
                    mma16816(sc[nb], qf[2*p+1][0], qf[2*p+1][1], qf[2*p+1][2], qf[2*p+1][3], b[2], b[3]);
                }
            }
        }

        float mx0 = -INFINITY, mx1 = -INFINITY;
        #pragma unroll
        for (int nb = 0; nb < 8; nb++) {
            mx0 = fmaxf(mx0, fmaxf(sc[nb][0], sc[nb][1]));
            mx1 = fmaxf(mx1, fmaxf(sc[nb][2], sc[nb][3]));
        }
        #pragma unroll
        for (int off = 1; off < 4; off <<= 1) {
            mx0 = fmaxf(mx0, __shfl_xor_sync(0xffffffffu, mx0, off));
            mx1 = fmaxf(mx1, __shfl_xor_sync(0xffffffffu, mx1, off));
        }
        float mn0 = fmaxf(m0, mx0), mn1 = fmaxf(m1, mx1);
        float fac0 = ex2f((m0 - mn0) * kS), fac1 = ex2f((m1 - mn1) * kS);
        m0 = mn0; m1 = mn1;
        float nm0 = m0 * kS, nm1 = m1 * kS;

        uint32_t ph[8][2];
        float ps0 = 0.f, ps1 = 0.f;
        #pragma unroll
        for (int nb = 0; nb < 8; nb++) {
            float e0 = ex2f(fmaf(sc[nb][0], kS, -nm0));
            float e1 = ex2f(fmaf(sc[nb][1], kS, -nm0));
            float e2 = ex2f(fmaf(sc[nb][2], kS, -nm1));
            float e3 = ex2f(fmaf(sc[nb][3], kS, -nm1));
            ps0 += e0 + e1; ps1 += e2 + e3;
            ph[nb][0] = h2u(e0, e1);
            ph[nb][1] = h2u(e2, e3);
        }
        #pragma unroll
        for (int off = 1; off < 4; off <<= 1) {
            ps0 += __shfl_xor_sync(0xffffffffu, ps0, off);
            ps1 += __shfl_xor_sync(0xffffffffu, ps1, off);
        }
        l0 = l0 * fac0 + ps0;
        l1 = l1 * fac1 + ps1;
        #pragma unroll
        for (int db = 0; db < 8; db++) {
            o[db][0] *= fac0; o[db][1] *= fac0;
            o[db][2] *= fac1; o[db][3] *= fac1;
        }

        {
            int rowl = lane & 7;
            int gl   = lane >> 3;
            #pragma unroll
            for (int kb2 = 0; kb2 < 4; kb2++) {
                uint32_t a0 = ph[2*kb2][0],   a1 = ph[2*kb2][1];
                uint32_t a2 = ph[2*kb2+1][0], a3 = ph[2*kb2+1][1];
                #pragma unroll
                for (int dbp = 0; dbp < 4; dbp++) {
                    uint32_t b[4];
                    uint32_t ad = smaddr(Vs + (kb2*16 + (gl & 1)*8 + rowl)*LDSH
                                            + dbp*16 + (gl >> 1)*8);
                    ldsm4t(b, ad);
                    mma16816(o[2*dbp+0], a0, a1, a2, a3, b[0], b[1]);
                    mma16816(o[2*dbp+1], a0, a1, a2, a3, b[2], b[3]);
                }
            }
        }
        __syncthreads();
    }

    // ---- normalize + write to concat [B,T,768] fp16 ----
    int b_ = bh / HH, h_ = bh % HH;
    float inv0 = 1.0f / l0, inv1 = 1.0f / l1;
    int r0 = q0 + wrow + (lane >> 2);
    int r1 = r0 + 8;
    int colb = h_*64 + (lane & 3)*2;
    __half* base0 = g_cat + (size_t)(b_*TT + r0)*DM + colb;
    __half* base1 = g_cat + (size_t)(b_*TT + r1)*DM + colb;
    #pragma unroll
    for (int db = 0; db < 8; db++) {
        *(__half2*)(base0 + db*8) = __floats2half2_rn(o[db][0]*inv0, o[db][1]*inv0);
        *(__half2*)(base1 + db*8) = __floats2half2_rn(o[db][2]*inv1, o[db][3]*inv1);
    }
}

// ---------------------------------------------------------------------------
// Kernel 3: output projection with fp16 mma: out = cat @ Wo^T + bo
// grid (DM/128, BT/128), block 256 (8 warps). 128x128 C tile, k=768 in 12
// chunks of 64, double-buffered cp.async.
// ---------------------------------------------------------------------------
#define OP_LDSH 72
#define OP_MAT  (128*OP_LDSH)                 // halfs per matrix buffer
#define SMEM_OP (4*OP_MAT*2)                  // bytes = 73728

__global__ __launch_bounds__(256) void outproj_kernel(
    const float* __restrict__ bo, float* __restrict__ outp)
{
    extern __shared__ __half sm2[];
    const int t    = threadIdx.x;
    const int lane = t & 31;
    const int wid  = t >> 5;
    const int wrow = wid * 16;
    const int m0 = blockIdx.x * 128;
    const int n0 = blockIdx.y * 128;

    {
        __half* As = sm2;
        __half* Bs = As + OP_MAT;
        #pragma unroll
        for (int i = 0; i < 4; i++) {
            int c = t + i*256;
            int row = c >> 3, off = (c & 7) * 8;
            cp16(As + row*OP_LDSH + off, g_cat + (size_t)(n0 + row)*DM + off);
            cp16(Bs + row*OP_LDSH + off, g_woh + (size_t)(m0 + row)*DM + off);
        }
        cp_commit();
    }

    float c[16][4] = {};
    const int NC = DM / 64;   // 12
    for (int it = 0; it < NC; it++) {
        int st = it & 1;
        __half* As = sm2 + st*2*OP_MAT;
        __half* Bs = As + OP_MAT;

        if (it + 1 < NC) {
            int k0 = (it+1) * 64;
            __half* An = sm2 + ((it+1)&1)*2*OP_MAT;
            __half* Bn = An + OP_MAT;
            #pragma unroll
            for (int i = 0; i < 4; i++) {
                int cc = t + i*256;
                int row = cc >> 3, off = (cc & 7) * 8;
                cp16(An + row*OP_LDSH + off, g_cat + (size_t)(n0 + row)*DM + k0 + off);
                cp16(Bn + row*OP_LDSH + off, g_woh + (size_t)(m0 + row)*DM + k0 + off);
            }
            cp_commit();
            cp_wait<1>();
        } else {
            cp_wait<0>();
        }
        __syncthreads();

        uint32_t af[4][4];
        {
            int rowl = ((lane >> 3) & 1) * 8 + (lane & 7);
            int coll = (lane >> 4) * 8;
            #pragma unroll
            for (int kb = 0; kb < 4; kb++) {
                uint32_t a = smaddr(As + (wrow + rowl)*OP_LDSH + kb*16 + coll);
                ldsm4(af[kb], a);
            }
        }

        {
            int rowb = lane & 7;
            int gl   = lane >> 3;
            #pragma unroll
            for (int nb = 0; nb < 16; nb++) {
                #pragma unroll
                for (int p = 0; p < 2; p++) {
                    uint32_t b[4];
                    uint32_t a = smaddr(Bs + (nb*8 + rowb)*OP_LDSH + p*32 + gl*8);
                    ldsm4(b, a);
                    mma16816(c[nb], af[2*p+0][0], af[2*p+0][1], af[2*p+0][2], af[2*p+0][3], b[0], b[1]);
                    mma16816(c[nb], af[2*p+1][0], af[2*p+1][1], af[2*p+1][2], af[2*p+1][3], b[2], b[3]);
                }
            }
        }
        __syncthreads();
    }

    int r0 = n0 + wrow + (lane >> 2);
    int r1 = r0 + 8;
    #pragma unroll
    for (int nb = 0; nb < 16; nb++) {
        int col = m0 + nb*8 + (lane & 3)*2;
        float b0 = bo[col], b1 = bo[col + 1];
        *(float2*)(outp + (size_t)r0*DM + col) = make_float2(c[nb][0] + b0, c[nb][1] + b1);
        *(float2*)(outp + (size_t)r1*DM + col) = make_float2(c[nb][2] + b0, c[nb][3] + b1);
    }
}

// ---------------------------------------------------------------------------
extern "C" void kernel_launch(void* const* d_in, const int* in_sizes, int n_in,
                              void* d_out, int out_size)
{
    const float* q  = (const float*)d_in[0];
    const float* k  = (const float*)d_in[1];
    const float* v  = (const float*)d_in[2];
    const float* Wq = (const float*)d_in[3];
    const float* bq = (const float*)d_in[4];
    const float* Wk = (const float*)d_in[5];
    const float* bk = (const float*)d_in[6];
    const float* Wv = (const float*)d_in[7];
    const float* bv = (const float*)d_in[8];
    const float* Wo = (const float*)d_in[9];
    const float* bo = (const float*)d_in[10];
    float* outp = (float*)d_out;

    cudaFuncSetAttribute(attn_kernel, cudaFuncAttributeMaxDynamicSharedMemorySize, SMEM_ATTN);
    cudaFuncSetAttribute(outproj_kernel, cudaFuncAttributeMaxDynamicSharedMemorySize, SMEM_OP);

    convert_wo_kernel<<<DM*DM/4/256, 256>>>(Wo);
    proj_kernel<<<dim3(BT*HH/128, 1, 3), 256>>>(q, k, v, Wq, bq, Wk, bk, Wv, bv);
    attn_kernel<<<dim3(TT/128, BB*HH), 256, SMEM_ATTN>>>();
    outproj_kernel<<<dim3(DM/128, BT/128), 256, SMEM_OP>>>(bo, outp);
}